// round 13
// baseline (speedup 1.0000x reference)
#include <cuda_runtime.h>
#include <cuda_fp16.h>
#include <cstdint>
#include <math.h>

#define NTOK   49
#define HEADS  6
#define DIM    192
#define DH     32
#define QSCALE 0.1767766952966369f

/* ================= device scratch (static: allocation-free) ================= */
__device__ __half  g_qhi[200704u * 576u];   /* qkv hi (q pre-scaled) 231 MB */
__device__ __half  g_qlo[200704u * 192u];   /* q lo only             77 MB  */
__device__ __half  g_ahi[200704u * 192u];   /* attention out hi      77 MB  */
__device__ __half  g_alo[200704u * 192u];   /* attention out lo      77 MB  */
__device__ __half  g_wq[576 * 192];
__device__ __half  g_wp[192 * 192];
__device__ float   g_bias[HEADS * NTOK * NTOK];

__device__ __forceinline__ uint32_t hpack(__half a, __half b) {
    return (uint32_t)__half_as_ushort(a) | ((uint32_t)__half_as_ushort(b) << 16);
}

/* ================= prep: weights -> fp16 (RN), materialize bias ================= */
__global__ void prep_kernel(const float* __restrict__ qkv_w, const float* __restrict__ proj_w,
                            const float* __restrict__ bias_table, const int* __restrict__ rel_idx)
{
    int i = blockIdx.x * 256 + threadIdx.x;
    if (i < 576 * 192) g_wq[i] = __float2half_rn(qkv_w[i]);
    if (i < 192 * 192) g_wp[i] = __float2half_rn(proj_w[i]);
    if (i < HEADS * NTOK * NTOK) {
        int m = i % NTOK, t = i / NTOK;
        int n = t % NTOK, h = t / NTOK;
        g_bias[i] = bias_table[rel_idx[n * NTOK + m] * HEADS + h];
    }
}

/* ================= mma fp16 / cp.async ================= */
__device__ __forceinline__ void mma16816(float* c, const uint32_t* a, const uint32_t* b) {
    asm volatile(
        "mma.sync.aligned.m16n8k16.row.col.f32.f16.f16.f32 "
        "{%0,%1,%2,%3}, {%4,%5,%6,%7}, {%8,%9}, {%0,%1,%2,%3};"
        : "+f"(c[0]), "+f"(c[1]), "+f"(c[2]), "+f"(c[3])
        : "r"(a[0]), "r"(a[1]), "r"(a[2]), "r"(a[3]), "r"(b[0]), "r"(b[1]));
}
__device__ __forceinline__ void cp16(uint32_t dst, const void* src) {
    asm volatile("cp.async.cg.shared.global [%0], [%1], 16;" :: "r"(dst), "l"(src));
}

/* ================ GEMM (R12 skeleton + modes) ================
   mode 0 (qkv): A fp32 -> converted once; epilogue -> pre-split fp16 (Ohi 576 cols,
                 q cols pre-scaled; Olo for q cols).
   mode 1 (proj): A pre-split fp16 (Ahi/Alo) loaded via cp.async; epilogue -> fp32 C. */
#define APAD   200
#define A_H    0
#define A_L    (128 * APAD * 2)                /* 51200  */
#define B_BASE (2 * 128 * APAD * 2)            /* 102400 */
#define B_STEP 27648
#define GEMM_SMEM (B_BASE + 2 * B_STEP)        /* 157696 */

__global__ __launch_bounds__(256, 1)
void gemm_fp16x2(const float* __restrict__ A,
                 const __half* __restrict__ Ahi, const __half* __restrict__ Alo,
                 const __half* __restrict__ B,
                 const float* __restrict__ bias,
                 float* __restrict__ C,
                 __half* __restrict__ Ohi, __half* __restrict__ Olo,
                 int ldc, int NT, int mode)
{
    extern __shared__ char smc[];
    uint32_t sb;
    asm("{ .reg .u64 t; cvta.to.shared.u64 t, %1; cvt.u32.u64 %0, t; }" : "=r"(sb) : "l"(smc));

    const int tid = threadIdx.x, wid = tid >> 5, lane = tid & 31;
    const int mtile = blockIdx.x;
    const int wm = (wid & 3) * 32;
    const int wn = (wid >> 2) * 96;
    const int L  = 3 * NT;

    auto prefetch = [&](int idx) {
        int nt = idx / 3, kc = idx - nt * 3;
        const __half* bp = B + (size_t)nt * 192 * 192 + kc * 64;
        uint32_t dst = sb + B_BASE + (idx & 1) * B_STEP;
        #pragma unroll
        for (int it = 0; it < 6; it++) {
            int g = tid + it * 256;
            int row = g >> 3, c8 = g & 7;
            cp16(dst + row * 144 + c8 * 16, bp + row * 192 + c8 * 8);
        }
        asm volatile("cp.async.commit_group;" ::: "memory");
    };

    if (mode == 1) {
        /* A pre-split: async copy into A_H / A_L (group 0) */
        const __half* Ah = Ahi + (size_t)mtile * 128 * 192;
        const __half* Al = Alo + (size_t)mtile * 128 * 192;
        #pragma unroll
        for (int it = 0; it < 12; it++) {
            int g = tid + it * 256;            /* 3072 chunks of 16 B per half */
            int row = g / 24, c = g % 24;
            cp16(sb + A_H + row * 400 + c * 16, Ah + row * 192 + c * 8);
            cp16(sb + A_L + row * 400 + c * 16, Al + row * 192 + c * 8);
        }
        asm volatile("cp.async.commit_group;" ::: "memory");
        prefetch(0);
        if (L > 1) prefetch(1);
    } else {
        prefetch(0);
        if (L > 1) prefetch(1);
        /* A fp32 -> hi/lo fp16, once */
        const float* Abase = A + (size_t)mtile * 128 * 192;
        #pragma unroll
        for (int it = 0; it < 24; it++) {
            int g = tid + it * 256;
            int row = g / 48, c4 = (g % 48) * 4;
            float4 f = *(const float4*)(Abase + row * 192 + c4);
            __half hx = __float2half_rn(f.x), hy = __float2half_rn(f.y);
            __half hz = __float2half_rn(f.z), hw = __float2half_rn(f.w);
            float rx = f.x - __half2float(hx);
            float ry = f.y - __half2float(hy);
            float rz = f.z - __half2float(hz);
            float rw = f.w - __half2float(hw);
            *(uint2*)(smc + A_H + row * 400 + c4 * 2) =
                make_uint2(hpack(hx, hy), hpack(hz, hw));
            *(uint2*)(smc + A_L + row * 400 + c4 * 2) =
                make_uint2(hpack(__float2half_rn(rx), __float2half_rn(ry)),
                           hpack(__float2half_rn(rz), __float2half_rn(rw)));
        }
    }
    __syncthreads();

    float acc[2][12][4];

    for (int nt = 0; nt < NT; nt++) {
        #pragma unroll
        for (int mf = 0; mf < 2; mf++)
            #pragma unroll
            for (int nf = 0; nf < 12; nf++)
                #pragma unroll
                for (int j = 0; j < 4; j++) acc[mf][nf][j] = 0.f;

        for (int kc = 0; kc < 3; kc++) {
            const int idx = nt * 3 + kc;
            if (idx < L - 1) asm volatile("cp.async.wait_group 1;" ::: "memory");
            else             asm volatile("cp.async.wait_group 0;" ::: "memory");
            __syncthreads();

            const char* bb = smc + B_BASE + (idx & 1) * B_STEP;

            #pragma unroll
            for (int ks = 0; ks < 4; ks++) {
                const int kk  = ks * 16 + (lane & 3) * 2;
                const int kxg = kc * 64 + kk;

                uint32_t ah[2][4], al[2][4];
                #pragma unroll
                for (int mf = 0; mf < 2; mf++)
                    #pragma unroll
                    for (int j = 0; j < 4; j++) {
                        int rr = wm + mf * 16 + (lane >> 2) + (j & 1) * 8;
                        int kx = kxg + (j >> 1) * 8;
                        ah[mf][j] = *(const uint32_t*)(smc + A_H + rr * 400 + kx * 2);
                        al[mf][j] = *(const uint32_t*)(smc + A_L + rr * 400 + kx * 2);
                    }

                uint32_t bh[12][2];
                #pragma unroll
                for (int nf = 0; nf < 12; nf++) {
                    int n = wn + nf * 8 + (lane >> 2);
                    bh[nf][0] = *(const uint32_t*)(bb + n * 144 + kk * 2);
                    bh[nf][1] = *(const uint32_t*)(bb + n * 144 + (kk + 8) * 2);
                }

                #pragma unroll
                for (int mf = 0; mf < 2; mf++)
                    #pragma unroll
                    for (int nf = 0; nf < 12; nf++) {
                        mma16816(acc[mf][nf], ah[mf], bh[nf]);
                        mma16816(acc[mf][nf], al[mf], bh[nf]);
                    }
            }
            __syncthreads();
            if (idx + 2 < L) prefetch(idx + 2);
        }

        /* ---- epilogue ---- */
        if (mode == 0) {
            const int qcol = (nt == 0);
            #pragma unroll
            for (int mf = 0; mf < 2; mf++) {
                size_t r = (size_t)mtile * 128 + wm + mf * 16 + (lane >> 2);
                #pragma unroll
                for (int nf = 0; nf < 12; nf++) {
                    int cl = wn + nf * 8 + (lane & 3) * 2;      /* col within ntile */
                    int c  = nt * 192 + cl;                      /* global col (576) */
                    float b0 = __ldg(bias + c), b1 = __ldg(bias + c + 1);
                    float v0 = acc[mf][nf][0] + b0, v1 = acc[mf][nf][1] + b1;
                    float w0 = acc[mf][nf][2] + b0, w1 = acc[mf][nf][3] + b1;
                    if (qcol) { v0 *= QSCALE; v1 *= QSCALE; w0 *= QSCALE; w1 *= QSCALE; }
                    __half h0 = __float2half_rn(v0), h1 = __float2half_rn(v1);
                    __half g0 = __float2half_rn(w0), g1 = __float2half_rn(w1);
                    *(uint32_t*)&g_qhi[r * 576 + c]       = hpack(h0, h1);
                    *(uint32_t*)&g_qhi[(r + 8) * 576 + c] = hpack(g0, g1);
                    if (qcol) {
                        *(uint32_t*)&g_qlo[r * 192 + cl] =
                            hpack(__float2half_rn(v0 - __half2float(h0)),
                                  __float2half_rn(v1 - __half2float(h1)));
                        *(uint32_t*)&g_qlo[(r + 8) * 192 + cl] =
                            hpack(__float2half_rn(w0 - __half2float(g0)),
                                  __float2half_rn(w1 - __half2float(g1)));
                    }
                }
            }
        } else {
            #pragma unroll
            for (int mf = 0; mf < 2; mf++) {
                size_t r0 = (size_t)mtile * 128 + wm + mf * 16 + (lane >> 2);
                #pragma unroll
                for (int nf = 0; nf < 12; nf++) {
                    int c = nt * 192 + wn + nf * 8 + (lane & 3) * 2;
                    float b0 = __ldg(bias + c), b1 = __ldg(bias + c + 1);
                    *(float2*)(C + r0 * ldc + c) =
                        make_float2(acc[mf][nf][0] + b0, acc[mf][nf][1] + b1);
                    *(float2*)(C + (r0 + 8) * ldc + c) =
                        make_float2(acc[mf][nf][2] + b0, acc[mf][nf][3] + b1);
                }
            }
        }
    }
}

/* ================= K2: R12-shape attention, pre-split fp16 inputs ================= */
__global__ __launch_bounds__(128, 3)
void attn_win()
{
    __shared__ __half sQh[64 * 36], sQl[64 * 36];
    __shared__ __half sKh[56 * 36];
    __shared__ __half sVh[32 * 66];

    const int tid  = threadIdx.x;
    const int wid  = tid >> 5, lane = tid & 31;
    const int b    = blockIdx.x;
    const int l4   = lane >> 2, lm = lane & 3;

    for (int i = tid; i < 64 * 36; i += 128) { sQh[i] = __ushort_as_half(0); sQl[i] = __ushort_as_half(0); }
    for (int i = tid; i < 56 * 36; i += 128) sKh[i] = __ushort_as_half(0);
    for (int i = tid; i < 32 * 66; i += 128) sVh[i] = __ushort_as_half(0);

    const __half* qhi = g_qhi + (size_t)b * (NTOK * 576);
    const __half* qlo = g_qlo + (size_t)b * (NTOK * 192);
    const int r0 = wid * 16 + l4;

    for (int h = 0; h < HEADS; h++) {
        __syncthreads();
        /* ---- load phase: pure fp16 copies (no conversion math) ---- */
        for (int idx = tid; idx < NTOK * 16; idx += 128) {
            int r = idx >> 4, c2 = (idx & 15) << 1;
            uint32_t q2 = *(const uint32_t*)&qhi[r * 576 + h * 32 + c2];
            uint32_t l2 = *(const uint32_t*)&qlo[r * 192 + h * 32 + c2];
            uint32_t k2 = *(const uint32_t*)&qhi[r * 576 + 192 + h * 32 + c2];
            uint32_t v2 = *(const uint32_t*)&qhi[r * 576 + 384 + h * 32 + c2];
            *(uint32_t*)&sQh[r * 36 + c2] = q2;
            *(uint32_t*)&sQl[r * 36 + c2] = l2;
            *(uint32_t*)&sKh[r * 36 + c2] = k2;
            sVh[c2 * 66 + r]       = __ushort_as_half((unsigned short)(v2 & 0xffffu));
            sVh[(c2 + 1) * 66 + r] = __ushort_as_half((unsigned short)(v2 >> 16));
        }
        __syncthreads();

        /* ---- Q a-frags ---- */
        uint32_t qh[2][4], ql[2][4];
        #pragma unroll
        for (int kf = 0; kf < 2; kf++)
            #pragma unroll
            for (int j = 0; j < 4; j++) {
                int rr = r0 + (j & 1) * 8;
                int kx = kf * 16 + lm * 2 + (j >> 1) * 8;
                qh[kf][j] = *(const uint32_t*)&sQh[rr * 36 + kx];
                ql[kf][j] = *(const uint32_t*)&sQl[rr * 36 + kx];
            }

        /* ---- S = Q K^T (2-term) ---- */
        float acc[7][4];
        #pragma unroll
        for (int nf = 0; nf < 7; nf++)
            #pragma unroll
            for (int j = 0; j < 4; j++) acc[nf][j] = 0.f;

        #pragma unroll
        for (int nf = 0; nf < 7; nf++) {
            int n = nf * 8 + l4;
            #pragma unroll
            for (int kf = 0; kf < 2; kf++) {
                uint32_t bh[2];
                bh[0] = *(const uint32_t*)&sKh[n * 36 + kf * 16 + lm * 2];
                bh[1] = *(const uint32_t*)&sKh[n * 36 + kf * 16 + lm * 2 + 8];
                mma16816(acc[nf], qh[kf], bh);
                mma16816(acc[nf], ql[kf], bh);
            }
        }

        /* ---- softmax ---- */
        const int ra = r0, rb = r0 + 8;
        const float* biasA = g_bias + (h * NTOK + ra) * NTOK;
        const float* biasB = g_bias + (h * NTOK + rb) * NTOK;
        float ma = -1e30f, mb = -1e30f;
        #pragma unroll
        for (int nf = 0; nf < 7; nf++) {
            int c0 = nf * 8 + lm * 2, c1 = c0 + 1;
            float ba0 = (ra < NTOK && c0 < NTOK) ? __ldg(biasA + c0) : 0.f;
            float ba1 = (ra < NTOK && c1 < NTOK) ? __ldg(biasA + c1) : 0.f;
            float bb0 = (rb < NTOK && c0 < NTOK) ? __ldg(biasB + c0) : 0.f;
            float bb1 = (rb < NTOK && c1 < NTOK) ? __ldg(biasB + c1) : 0.f;
            acc[nf][0] = (c0 < NTOK) ? acc[nf][0] + ba0 : -1e30f;
            acc[nf][1] = (c1 < NTOK) ? acc[nf][1] + ba1 : -1e30f;
            acc[nf][2] = (c0 < NTOK) ? acc[nf][2] + bb0 : -1e30f;
            acc[nf][3] = (c1 < NTOK) ? acc[nf][3] + bb1 : -1e30f;
            ma = fmaxf(ma, fmaxf(acc[nf][0], acc[nf][1]));
            mb = fmaxf(mb, fmaxf(acc[nf][2], acc[nf][3]));
        }
        ma = fmaxf(ma, __shfl_xor_sync(0xffffffffu, ma, 1));
        ma = fmaxf(ma, __shfl_xor_sync(0xffffffffu, ma, 2));
        mb = fmaxf(mb, __shfl_xor_sync(0xffffffffu, mb, 1));
        mb = fmaxf(mb, __shfl_xor_sync(0xffffffffu, mb, 2));

        float sa = 0.f, sb2 = 0.f;
        #pragma unroll
        for (int nf = 0; nf < 7; nf++) {
            acc[nf][0] = __expf(acc[nf][0] - ma);
            acc[nf][1] = __expf(acc[nf][1] - ma);
            acc[nf][2] = __expf(acc[nf][2] - mb);
            acc[nf][3] = __expf(acc[nf][3] - mb);
            sa  += acc[nf][0] + acc[nf][1];
            sb2 += acc[nf][2] + acc[nf][3];
        }
        sa  += __shfl_xor_sync(0xffffffffu, sa, 1);
        sa  += __shfl_xor_sync(0xffffffffu, sa, 2);
        sb2 += __shfl_xor_sync(0xffffffffu, sb2, 1);
        sb2 += __shfl_xor_sync(0xffffffffu, sb2, 2);
        float inva = 1.f / sa, invb = 1.f / sb2;
        #pragma unroll
        for (int nf = 0; nf < 7; nf++) {
            acc[nf][0] *= inva; acc[nf][1] *= inva;
            acc[nf][2] *= invb; acc[nf][3] *= invb;
        }

        /* ---- P hi/lo a-frags ---- */
        uint32_t pah[4][4], pal[4][4];
        #pragma unroll
        for (int kf = 0; kf < 4; kf++) {
            #pragma unroll
            for (int half = 0; half < 2; half++) {
                int nf = 2 * kf + half;
                if (nf < 7) {
                    float p0 = acc[nf][0], p1 = acc[nf][1];
                    float p2 = acc[nf][2], p3 = acc[nf][3];
                    __half h0 = __float2half_rn(p0), h1 = __float2half_rn(p1);
                    __half h2 = __float2half_rn(p2), h3 = __float2half_rn(p3);
                    pah[kf][half * 2]     = hpack(h0, h1);
                    pah[kf][half * 2 + 1] = hpack(h2, h3);
                    pal[kf][half * 2]     = hpack(__float2half_rn(p0 - __half2float(h0)),
                                                  __float2half_rn(p1 - __half2float(h1)));
                    pal[kf][half * 2 + 1] = hpack(__float2half_rn(p2 - __half2float(h2)),
                                                  __float2half_rn(p3 - __half2float(h3)));
                } else {
                    pah[kf][half * 2] = 0u; pah[kf][half * 2 + 1] = 0u;
                    pal[kf][half * 2] = 0u; pal[kf][half * 2 + 1] = 0u;
                }
            }
        }

        /* ---- O = P V (2-term) ---- */
        float oacc[4][4];
        #pragma unroll
        for (int nf = 0; nf < 4; nf++)
            #pragma unroll
            for (int j = 0; j < 4; j++) oacc[nf][j] = 0.f;

        #pragma unroll
        for (int nf = 0; nf < 4; nf++) {
            int dh = nf * 8 + l4;
            #pragma unroll
            for (int kf = 0; kf < 4; kf++) {
                uint32_t bh[2];
                bh[0] = *(const uint32_t*)&sVh[dh * 66 + kf * 16 + lm * 2];
                bh[1] = *(const uint32_t*)&sVh[dh * 66 + kf * 16 + lm * 2 + 8];
                mma16816(oacc[nf], pah[kf], bh);
                mma16816(oacc[nf], pal[kf], bh);
            }
        }

        /* ---- store O pre-split fp16 ---- */
        if (ra < NTOK) {
            size_t base = ((size_t)(b * NTOK + ra)) * DIM + h * DH;
            #pragma unroll
            for (int nf = 0; nf < 4; nf++) {
                float v0 = oacc[nf][0], v1 = oacc[nf][1];
                __half h0 = __float2half_rn(v0), h1 = __float2half_rn(v1);
                *(uint32_t*)&g_ahi[base + nf * 8 + lm * 2] = hpack(h0, h1);
                *(uint32_t*)&g_alo[base + nf * 8 + lm * 2] =
                    hpack(__float2half_rn(v0 - __half2float(h0)),
                          __float2half_rn(v1 - __half2float(h1)));
            }
        }
        if (rb < NTOK) {
            size_t base = ((size_t)(b * NTOK + rb)) * DIM + h * DH;
            #pragma unroll
            for (int nf = 0; nf < 4; nf++) {
                float v0 = oacc[nf][2], v1 = oacc[nf][3];
                __half h0 = __float2half_rn(v0), h1 = __float2half_rn(v1);
                *(uint32_t*)&g_ahi[base + nf * 8 + lm * 2] = hpack(h0, h1);
                *(uint32_t*)&g_alo[base + nf * 8 + lm * 2] =
                    hpack(__float2half_rn(v0 - __half2float(h0)),
                          __float2half_rn(v1 - __half2float(h1)));
            }
        }
    }
}

/* ================= host ================= */
extern "C" void kernel_launch(void* const* d_in, const int* in_sizes, int n_in,
                              void* d_out, int out_size)
{
    const float* x          = (const float*)d_in[0];
    const float* qkv_w      = (const float*)d_in[1];
    const float* qkv_b      = (const float*)d_in[2];
    const float* proj_w     = (const float*)d_in[3];
    const float* proj_b     = (const float*)d_in[4];
    const float* bias_table = (const float*)d_in[5];
    const int*   rel_idx    = (const int*)d_in[6];
    float*       out        = (float*)d_out;

    const int nB = in_sizes[0] / (NTOK * DIM);       /* 4096 */
    const int mt = (nB * NTOK) / 128;                /* 1568 */

    void *p_wq, *p_wp, *p_ahi, *p_alo;
    cudaGetSymbolAddress(&p_wq,  g_wq);
    cudaGetSymbolAddress(&p_wp,  g_wp);
    cudaGetSymbolAddress(&p_ahi, g_ahi);
    cudaGetSymbolAddress(&p_alo, g_alo);

    cudaFuncSetAttribute(gemm_fp16x2, cudaFuncAttributeMaxDynamicSharedMemorySize, GEMM_SMEM);

    prep_kernel<<<432, 256>>>(qkv_w, proj_w, bias_table, rel_idx);

    /* qkv: fp32 A -> pre-split fp16 out (mode 0) */
    gemm_fp16x2<<<mt, 256, GEMM_SMEM>>>(
        x, nullptr, nullptr, (const __half*)p_wq, qkv_b,
        nullptr, nullptr, nullptr, 576, 3, 0);

    attn_win<<<nB, 128>>>();

    /* proj: pre-split fp16 A -> fp32 out (mode 1) */
    gemm_fp16x2<<<mt, 256, GEMM_SMEM>>>(
        nullptr, (const __half*)p_ahi, (const __half*)p_alo, (const __half*)p_wp, proj_b,
        out, nullptr, nullptr, 192, 1, 1);
}

// round 14
// speedup vs baseline: 1.0047x; 1.0047x over previous
#include <cuda_runtime.h>
#include <cuda_fp16.h>
#include <cstdint>
#include <math.h>

#define NTOK   49
#define HEADS  6
#define DIM    192
#define DH     32
#define QSCALE 0.1767766952966369f

/* ================= device scratch (static: allocation-free) ================= */
__device__ __half  g_qhi[200704u * 576u];   /* qkv hi (q pre-scaled) 231 MB */
__device__ __half  g_qlo[200704u * 192u];   /* q lo only             77 MB  */
__device__ __half  g_ahi[200704u * 192u];   /* attention out hi      77 MB  */
__device__ __half  g_alo[200704u * 192u];   /* attention out lo      77 MB  */
__device__ __half  g_wq[576 * 192];
__device__ __half  g_wp[192 * 192];
__device__ float   g_bias[HEADS * NTOK * NTOK];

__device__ __forceinline__ uint32_t hpack(__half a, __half b) {
    return (uint32_t)__half_as_ushort(a) | ((uint32_t)__half_as_ushort(b) << 16);
}

/* ================= prep ================= */
__global__ void prep_kernel(const float* __restrict__ qkv_w, const float* __restrict__ proj_w,
                            const float* __restrict__ bias_table, const int* __restrict__ rel_idx)
{
    int i = blockIdx.x * 256 + threadIdx.x;
    if (i < 576 * 192) g_wq[i] = __float2half_rn(qkv_w[i]);
    if (i < 192 * 192) g_wp[i] = __float2half_rn(proj_w[i]);
    if (i < HEADS * NTOK * NTOK) {
        int m = i % NTOK, t = i / NTOK;
        int n = t % NTOK, h = t / NTOK;
        g_bias[i] = bias_table[rel_idx[n * NTOK + m] * HEADS + h];
    }
}

/* ================= mma fp16 / cp.async ================= */
__device__ __forceinline__ void mma16816(float* c, const uint32_t* a, const uint32_t* b) {
    asm volatile(
        "mma.sync.aligned.m16n8k16.row.col.f32.f16.f16.f32 "
        "{%0,%1,%2,%3}, {%4,%5,%6,%7}, {%8,%9}, {%0,%1,%2,%3};"
        : "+f"(c[0]), "+f"(c[1]), "+f"(c[2]), "+f"(c[3])
        : "r"(a[0]), "r"(a[1]), "r"(a[2]), "r"(a[3]), "r"(b[0]), "r"(b[1]));
}
__device__ __forceinline__ void cp16(uint32_t dst, const void* src) {
    asm volatile("cp.async.cg.shared.global [%0], [%1], 16;" :: "r"(dst), "l"(src));
}

/* ================ shared GEMM constants ================ */
#define APAD   200
#define A_H    0
#define A_L    (128 * APAD * 2)                /* 51200  */
#define B_BASE (2 * 128 * APAD * 2)            /* 102400 */
#define B_STEP 27648
#define GEMM_SMEM (B_BASE + 2 * B_STEP)        /* 157696 */

/* the shared mainloop (A already in smem, B double-buffered) */
#define GEMM_MAINLOOP(NT_, ACC_)                                                   \
    for (int kc = 0; kc < 3; kc++) {                                               \
        const int idx = nt * 3 + kc;                                               \
        if (idx < 3 * (NT_) - 1) asm volatile("cp.async.wait_group 1;" ::: "memory"); \
        else                     asm volatile("cp.async.wait_group 0;" ::: "memory"); \
        __syncthreads();                                                           \
        const char* bb = smc + B_BASE + (idx & 1) * B_STEP;                        \
        _Pragma("unroll")                                                          \
        for (int ks = 0; ks < 4; ks++) {                                           \
            const int kk  = ks * 16 + (lane & 3) * 2;                              \
            const int kxg = kc * 64 + kk;                                          \
            uint32_t ah[2][4], al[2][4];                                           \
            _Pragma("unroll")                                                      \
            for (int mf = 0; mf < 2; mf++)                                         \
                _Pragma("unroll")                                                  \
                for (int j = 0; j < 4; j++) {                                      \
                    int rr = wm + mf * 16 + (lane >> 2) + (j & 1) * 8;             \
                    int kx = kxg + (j >> 1) * 8;                                   \
                    ah[mf][j] = *(const uint32_t*)(smc + A_H + rr * 400 + kx * 2); \
                    al[mf][j] = *(const uint32_t*)(smc + A_L + rr * 400 + kx * 2); \
                }                                                                  \
            uint32_t bh[12][2];                                                    \
            _Pragma("unroll")                                                      \
            for (int nf = 0; nf < 12; nf++) {                                      \
                int n = wn + nf * 8 + (lane >> 2);                                 \
                bh[nf][0] = *(const uint32_t*)(bb + n * 144 + kk * 2);             \
                bh[nf][1] = *(const uint32_t*)(bb + n * 144 + (kk + 8) * 2);       \
            }                                                                      \
            _Pragma("unroll")                                                      \
            for (int mf = 0; mf < 2; mf++)                                         \
                _Pragma("unroll")                                                  \
                for (int nf = 0; nf < 12; nf++) {                                  \
                    mma16816(ACC_[mf][nf], ah[mf], bh[nf]);                        \
                    mma16816(ACC_[mf][nf], al[mf], bh[nf]);                        \
                }                                                                  \
        }                                                                          \
        __syncthreads();                                                           \
        if (idx + 2 < 3 * (NT_)) prefetch(idx + 2);                                \
    }

/* ================ K1: qkv GEMM (fp32 A in, pre-split fp16 out) ================ */
__global__ __launch_bounds__(256, 1)
void gemm_qkv(const float* __restrict__ A,
              const __half* __restrict__ B,
              const float* __restrict__ bias)
{
    extern __shared__ char smc[];
    uint32_t sb;
    asm("{ .reg .u64 t; cvta.to.shared.u64 t, %1; cvt.u32.u64 %0, t; }" : "=r"(sb) : "l"(smc));

    const int tid = threadIdx.x, wid = tid >> 5, lane = tid & 31;
    const int mtile = blockIdx.x;
    const int wm = (wid & 3) * 32;
    const int wn = (wid >> 2) * 96;

    auto prefetch = [&](int idx) {
        int nt = idx / 3, kc = idx - nt * 3;
        const __half* bp = B + (size_t)nt * 192 * 192 + kc * 64;
        uint32_t dst = sb + B_BASE + (idx & 1) * B_STEP;
        #pragma unroll
        for (int it = 0; it < 6; it++) {
            int g = tid + it * 256;
            int row = g >> 3, c8 = g & 7;
            cp16(dst + row * 144 + c8 * 16, bp + row * 192 + c8 * 8);
        }
        asm volatile("cp.async.commit_group;" ::: "memory");
    };

    prefetch(0);
    prefetch(1);

    /* A fp32 -> hi/lo fp16, once */
    {
        const float* Abase = A + (size_t)mtile * 128 * 192;
        #pragma unroll
        for (int it = 0; it < 24; it++) {
            int g = tid + it * 256;
            int row = g / 48, c4 = (g % 48) * 4;
            float4 f = *(const float4*)(Abase + row * 192 + c4);
            __half hx = __float2half_rn(f.x), hy = __float2half_rn(f.y);
            __half hz = __float2half_rn(f.z), hw = __float2half_rn(f.w);
            *(uint2*)(smc + A_H + row * 400 + c4 * 2) =
                make_uint2(hpack(hx, hy), hpack(hz, hw));
            *(uint2*)(smc + A_L + row * 400 + c4 * 2) =
                make_uint2(hpack(__float2half_rn(f.x - __half2float(hx)),
                                 __float2half_rn(f.y - __half2float(hy))),
                           hpack(__float2half_rn(f.z - __half2float(hz)),
                                 __float2half_rn(f.w - __half2float(hw))));
        }
    }
    __syncthreads();

    float acc[2][12][4];

    for (int nt = 0; nt < 3; nt++) {
        #pragma unroll
        for (int mf = 0; mf < 2; mf++)
            #pragma unroll
            for (int nf = 0; nf < 12; nf++)
                #pragma unroll
                for (int j = 0; j < 4; j++) acc[mf][nf][j] = 0.f;

        GEMM_MAINLOOP(3, acc)

        /* epilogue: pre-split fp16 out; q cols pre-scaled, lo kept for q only */
        const int qcol = (nt == 0);
        #pragma unroll
        for (int mf = 0; mf < 2; mf++) {
            size_t r = (size_t)mtile * 128 + wm + mf * 16 + (lane >> 2);
            #pragma unroll
            for (int nf = 0; nf < 12; nf++) {
                int cl = wn + nf * 8 + (lane & 3) * 2;
                int c  = nt * 192 + cl;
                float b0 = __ldg(bias + c), b1 = __ldg(bias + c + 1);
                float v0 = acc[mf][nf][0] + b0, v1 = acc[mf][nf][1] + b1;
                float w0 = acc[mf][nf][2] + b0, w1 = acc[mf][nf][3] + b1;
                if (qcol) { v0 *= QSCALE; v1 *= QSCALE; w0 *= QSCALE; w1 *= QSCALE; }
                __half h0 = __float2half_rn(v0), h1 = __float2half_rn(v1);
                __half g0 = __float2half_rn(w0), g1 = __float2half_rn(w1);
                *(uint32_t*)&g_qhi[r * 576 + c]       = hpack(h0, h1);
                *(uint32_t*)&g_qhi[(r + 8) * 576 + c] = hpack(g0, g1);
                if (qcol) {
                    *(uint32_t*)&g_qlo[r * 192 + cl] =
                        hpack(__float2half_rn(v0 - __half2float(h0)),
                              __float2half_rn(v1 - __half2float(h1)));
                    *(uint32_t*)&g_qlo[(r + 8) * 192 + cl] =
                        hpack(__float2half_rn(w0 - __half2float(g0)),
                              __float2half_rn(w1 - __half2float(g1)));
                }
            }
        }
    }
}

/* ================ K3: proj GEMM (pre-split fp16 A via cp.async, fp32 out) ================ */
__global__ __launch_bounds__(256, 1)
void gemm_proj(const __half* __restrict__ Ahi, const __half* __restrict__ Alo,
               const __half* __restrict__ B,
               const float* __restrict__ bias,
               float* __restrict__ C)
{
    extern __shared__ char smc[];
    uint32_t sb;
    asm("{ .reg .u64 t; cvta.to.shared.u64 t, %1; cvt.u32.u64 %0, t; }" : "=r"(sb) : "l"(smc));

    const int tid = threadIdx.x, wid = tid >> 5, lane = tid & 31;
    const int mtile = blockIdx.x;
    const int wm = (wid & 3) * 32;
    const int wn = (wid >> 2) * 96;

    auto prefetch = [&](int idx) {
        int kc = idx;                           /* NT = 1 */
        const __half* bp = B + kc * 64;
        uint32_t dst = sb + B_BASE + (idx & 1) * B_STEP;
        #pragma unroll
        for (int it = 0; it < 6; it++) {
            int g = tid + it * 256;
            int row = g >> 3, c8 = g & 7;
            cp16(dst + row * 144 + c8 * 16, bp + row * 192 + c8 * 8);
        }
        asm volatile("cp.async.commit_group;" ::: "memory");
    };

    /* A pre-split: async copy into A_H / A_L (group 0) */
    {
        const __half* Ah = Ahi + (size_t)mtile * 128 * 192;
        const __half* Al = Alo + (size_t)mtile * 128 * 192;
        #pragma unroll
        for (int it = 0; it < 12; it++) {
            int g = tid + it * 256;
            int row = g / 24, c = g % 24;
            cp16(sb + A_H + row * 400 + c * 16, Ah + row * 192 + c * 8);
            cp16(sb + A_L + row * 400 + c * 16, Al + row * 192 + c * 8);
        }
        asm volatile("cp.async.commit_group;" ::: "memory");
    }
    prefetch(0);
    prefetch(1);
    __syncthreads();

    float acc[2][12][4];
    {
        const int nt = 0;
        #pragma unroll
        for (int mf = 0; mf < 2; mf++)
            #pragma unroll
            for (int nf = 0; nf < 12; nf++)
                #pragma unroll
                for (int j = 0; j < 4; j++) acc[mf][nf][j] = 0.f;

        GEMM_MAINLOOP(1, acc)

        #pragma unroll
        for (int mf = 0; mf < 2; mf++) {
            size_t r0 = (size_t)mtile * 128 + wm + mf * 16 + (lane >> 2);
            #pragma unroll
            for (int nf = 0; nf < 12; nf++) {
                int c = wn + nf * 8 + (lane & 3) * 2;
                float b0 = __ldg(bias + c), b1 = __ldg(bias + c + 1);
                *(float2*)(C + r0 * 192 + c) =
                    make_float2(acc[mf][nf][0] + b0, acc[mf][nf][1] + b1);
                *(float2*)(C + (r0 + 8) * 192 + c) =
                    make_float2(acc[mf][nf][2] + b0, acc[mf][nf][3] + b1);
            }
        }
    }
}

/* ================= K2: attention, pre-split fp16 in, pre-split fp16 out ============ */
__global__ __launch_bounds__(128, 3)
void attn_win()
{
    __shared__ __half sQh[64 * 36], sQl[64 * 36];
    __shared__ __half sKh[56 * 36];
    __shared__ __half sVh[32 * 66];

    const int tid  = threadIdx.x;
    const int wid  = tid >> 5, lane = tid & 31;
    const int b    = blockIdx.x;
    const int l4   = lane >> 2, lm = lane & 3;

    for (int i = tid; i < 64 * 36; i += 128) { sQh[i] = __ushort_as_half(0); sQl[i] = __ushort_as_half(0); }
    for (int i = tid; i < 56 * 36; i += 128) sKh[i] = __ushort_as_half(0);
    for (int i = tid; i < 32 * 66; i += 128) sVh[i] = __ushort_as_half(0);

    const __half* qhi = g_qhi + (size_t)b * (NTOK * 576);
    const __half* qlo = g_qlo + (size_t)b * (NTOK * 192);
    const int r0 = wid * 16 + l4;

    for (int h = 0; h < HEADS; h++) {
        __syncthreads();
        for (int idx = tid; idx < NTOK * 16; idx += 128) {
            int r = idx >> 4, c2 = (idx & 15) << 1;
            uint32_t q2 = *(const uint32_t*)&qhi[r * 576 + h * 32 + c2];
            uint32_t l2 = *(const uint32_t*)&qlo[r * 192 + h * 32 + c2];
            uint32_t k2 = *(const uint32_t*)&qhi[r * 576 + 192 + h * 32 + c2];
            uint32_t v2 = *(const uint32_t*)&qhi[r * 576 + 384 + h * 32 + c2];
            *(uint32_t*)&sQh[r * 36 + c2] = q2;
            *(uint32_t*)&sQl[r * 36 + c2] = l2;
            *(uint32_t*)&sKh[r * 36 + c2] = k2;
            sVh[c2 * 66 + r]       = __ushort_as_half((unsigned short)(v2 & 0xffffu));
            sVh[(c2 + 1) * 66 + r] = __ushort_as_half((unsigned short)(v2 >> 16));
        }
        __syncthreads();

        uint32_t qh[2][4], ql[2][4];
        #pragma unroll
        for (int kf = 0; kf < 2; kf++)
            #pragma unroll
            for (int j = 0; j < 4; j++) {
                int rr = r0 + (j & 1) * 8;
                int kx = kf * 16 + lm * 2 + (j >> 1) * 8;
                qh[kf][j] = *(const uint32_t*)&sQh[rr * 36 + kx];
                ql[kf][j] = *(const uint32_t*)&sQl[rr * 36 + kx];
            }

        float acc[7][4];
        #pragma unroll
        for (int nf = 0; nf < 7; nf++)
            #pragma unroll
            for (int j = 0; j < 4; j++) acc[nf][j] = 0.f;

        #pragma unroll
        for (int nf = 0; nf < 7; nf++) {
            int n = nf * 8 + l4;
            #pragma unroll
            for (int kf = 0; kf < 2; kf++) {
                uint32_t bh[2];
                bh[0] = *(const uint32_t*)&sKh[n * 36 + kf * 16 + lm * 2];
                bh[1] = *(const uint32_t*)&sKh[n * 36 + kf * 16 + lm * 2 + 8];
                mma16816(acc[nf], qh[kf], bh);
                mma16816(acc[nf], ql[kf], bh);
            }
        }

        const int ra = r0, rb = r0 + 8;
        const float* biasA = g_bias + (h * NTOK + ra) * NTOK;
        const float* biasB = g_bias + (h * NTOK + rb) * NTOK;
        float ma = -1e30f, mb = -1e30f;
        #pragma unroll
        for (int nf = 0; nf < 7; nf++) {
            int c0 = nf * 8 + lm * 2, c1 = c0 + 1;
            float ba0 = (ra < NTOK && c0 < NTOK) ? __ldg(biasA + c0) : 0.f;
            float ba1 = (ra < NTOK && c1 < NTOK) ? __ldg(biasA + c1) : 0.f;
            float bb0 = (rb < NTOK && c0 < NTOK) ? __ldg(biasB + c0) : 0.f;
            float bb1 = (rb < NTOK && c1 < NTOK) ? __ldg(biasB + c1) : 0.f;
            acc[nf][0] = (c0 < NTOK) ? acc[nf][0] + ba0 : -1e30f;
            acc[nf][1] = (c1 < NTOK) ? acc[nf][1] + ba1 : -1e30f;
            acc[nf][2] = (c0 < NTOK) ? acc[nf][2] + bb0 : -1e30f;
            acc[nf][3] = (c1 < NTOK) ? acc[nf][3] + bb1 : -1e30f;
            ma = fmaxf(ma, fmaxf(acc[nf][0], acc[nf][1]));
            mb = fmaxf(mb, fmaxf(acc[nf][2], acc[nf][3]));
        }
        ma = fmaxf(ma, __shfl_xor_sync(0xffffffffu, ma, 1));
        ma = fmaxf(ma, __shfl_xor_sync(0xffffffffu, ma, 2));
        mb = fmaxf(mb, __shfl_xor_sync(0xffffffffu, mb, 1));
        mb = fmaxf(mb, __shfl_xor_sync(0xffffffffu, mb, 2));

        float sa = 0.f, sb2 = 0.f;
        #pragma unroll
        for (int nf = 0; nf < 7; nf++) {
            acc[nf][0] = __expf(acc[nf][0] - ma);
            acc[nf][1] = __expf(acc[nf][1] - ma);
            acc[nf][2] = __expf(acc[nf][2] - mb);
            acc[nf][3] = __expf(acc[nf][3] - mb);
            sa  += acc[nf][0] + acc[nf][1];
            sb2 += acc[nf][2] + acc[nf][3];
        }
        sa  += __shfl_xor_sync(0xffffffffu, sa, 1);
        sa  += __shfl_xor_sync(0xffffffffu, sa, 2);
        sb2 += __shfl_xor_sync(0xffffffffu, sb2, 1);
        sb2 += __shfl_xor_sync(0xffffffffu, sb2, 2);
        float inva = 1.f / sa, invb = 1.f / sb2;
        #pragma unroll
        for (int nf = 0; nf < 7; nf++) {
            acc[nf][0] *= inva; acc[nf][1] *= inva;
            acc[nf][2] *= invb; acc[nf][3] *= invb;
        }

        uint32_t pah[4][4], pal[4][4];
        #pragma unroll
        for (int kf = 0; kf < 4; kf++) {
            #pragma unroll
            for (int half = 0; half < 2; half++) {
                int nf = 2 * kf + half;
                if (nf < 7) {
                    float p0 = acc[nf][0], p1 = acc[nf][1];
                    float p2 = acc[nf][2], p3 = acc[nf][3];
                    __half h0 = __float2half_rn(p0), h1 = __float2half_rn(p1);
                    __half h2 = __float2half_rn(p2), h3 = __float2half_rn(p3);
                    pah[kf][half * 2]     = hpack(h0, h1);
                    pah[kf][half * 2 + 1] = hpack(h2, h3);
                    pal[kf][half * 2]     = hpack(__float2half_rn(p0 - __half2float(h0)),
                                                  __float2half_rn(p1 - __half2float(h1)));
                    pal[kf][half * 2 + 1] = hpack(__float2half_rn(p2 - __half2float(h2)),
                                                  __float2half_rn(p3 - __half2float(h3)));
                } else {
                    pah[kf][half * 2] = 0u; pah[kf][half * 2 + 1] = 0u;
                    pal[kf][half * 2] = 0u; pal[kf][half * 2 + 1] = 0u;
                }
            }
        }

        float oacc[4][4];
        #pragma unroll
        for (int nf = 0; nf < 4; nf++)
            #pragma unroll
            for (int j = 0; j < 4; j++) oacc[nf][j] = 0.f;

        #pragma unroll
        for (int nf = 0; nf < 4; nf++) {
            int dh = nf * 8 + l4;
            #pragma unroll
            for (int kf = 0; kf < 4; kf++) {
                uint32_t bh[2];
                bh[0] = *(const uint32_t*)&sVh[dh * 66 + kf * 16 + lm * 2];
                bh[1] = *(const uint32_t*)&sVh[dh * 66 + kf * 16 + lm * 2 + 8];
                mma16816(oacc[nf], pah[kf], bh);
                mma16816(oacc[nf], pal[kf], bh);
            }
        }

        if (ra < NTOK) {
            size_t base = ((size_t)(b * NTOK + ra)) * DIM + h * DH;
            #pragma unroll
            for (int nf = 0; nf < 4; nf++) {
                float v0 = oacc[nf][0], v1 = oacc[nf][1];
                __half h0 = __float2half_rn(v0), h1 = __float2half_rn(v1);
                *(uint32_t*)&g_ahi[base + nf * 8 + lm * 2] = hpack(h0, h1);
                *(uint32_t*)&g_alo[base + nf * 8 + lm * 2] =
                    hpack(__float2half_rn(v0 - __half2float(h0)),
                          __float2half_rn(v1 - __half2float(h1)));
            }
        }
        if (rb < NTOK) {
            size_t base = ((size_t)(b * NTOK + rb)) * DIM + h * DH;
            #pragma unroll
            for (int nf = 0; nf < 4; nf++) {
                float v0 = oacc[nf][2], v1 = oacc[nf][3];
                __half h0 = __float2half_rn(v0), h1 = __float2half_rn(v1);
                *(uint32_t*)&g_ahi[base + nf * 8 + lm * 2] = hpack(h0, h1);
                *(uint32_t*)&g_alo[base + nf * 8 + lm * 2] =
                    hpack(__float2half_rn(v0 - __half2float(h0)),
                          __float2half_rn(v1 - __half2float(h1)));
            }
        }
    }
}

/* ================= host ================= */
extern "C" void kernel_launch(void* const* d_in, const int* in_sizes, int n_in,
                              void* d_out, int out_size)
{
    const float* x          = (const float*)d_in[0];
    const float* qkv_w      = (const float*)d_in[1];
    const float* qkv_b      = (const float*)d_in[2];
    const float* proj_w     = (const float*)d_in[3];
    const float* proj_b     = (const float*)d_in[4];
    const float* bias_table = (const float*)d_in[5];
    const int*   rel_idx    = (const int*)d_in[6];
    float*       out        = (float*)d_out;

    const int nB = in_sizes[0] / (NTOK * DIM);       /* 4096 */
    const int mt = (nB * NTOK) / 128;                /* 1568 */

    void *p_wq, *p_wp, *p_ahi, *p_alo;
    cudaGetSymbolAddress(&p_wq,  g_wq);
    cudaGetSymbolAddress(&p_wp,  g_wp);
    cudaGetSymbolAddress(&p_ahi, g_ahi);
    cudaGetSymbolAddress(&p_alo, g_alo);

    cudaFuncSetAttribute(gemm_qkv,  cudaFuncAttributeMaxDynamicSharedMemorySize, GEMM_SMEM);
    cudaFuncSetAttribute(gemm_proj, cudaFuncAttributeMaxDynamicSharedMemorySize, GEMM_SMEM);

    prep_kernel<<<432, 256>>>(qkv_w, proj_w, bias_table, rel_idx);

    gemm_qkv<<<mt, 256, GEMM_SMEM>>>(x, (const __half*)p_wq, qkv_b);

    attn_win<<<nB, 128>>>();

    gemm_proj<<<mt, 256, GEMM_SMEM>>>((const __half*)p_ahi, (const __half*)p_alo,
                                      (const __half*)p_wp, proj_b, out);
}

// round 15
// speedup vs baseline: 1.0876x; 1.0825x over previous
#include <cuda_runtime.h>
#include <cuda_fp16.h>
#include <cstdint>
#include <math.h>

#define NTOK   49
#define HEADS  6
#define DIM    192
#define DH     32
#define QSCALE 0.1767766952966369f

/* ================= device scratch (static: allocation-free) ================= */
__device__ float   g_qkv [200704u * 576u];
__device__ float   g_attn[200704u * 192u];
__device__ __half  g_wq[576 * 192];
__device__ __half  g_wp[192 * 192];
__device__ float   g_bias[HEADS * NTOK * NTOK];

__device__ __forceinline__ uint32_t hpack(__half a, __half b) {
    return (uint32_t)__half_as_ushort(a) | ((uint32_t)__half_as_ushort(b) << 16);
}

/* ================= prep: weights -> fp16 (RN), materialize bias ================= */
__global__ void prep_kernel(const float* __restrict__ qkv_w, const float* __restrict__ proj_w,
                            const float* __restrict__ bias_table, const int* __restrict__ rel_idx)
{
    int i = blockIdx.x * 256 + threadIdx.x;
    if (i < 576 * 192) g_wq[i] = __float2half_rn(qkv_w[i]);
    if (i < 192 * 192) g_wp[i] = __float2half_rn(proj_w[i]);
    if (i < HEADS * NTOK * NTOK) {
        int m = i % NTOK, t = i / NTOK;
        int n = t % NTOK, h = t / NTOK;
        g_bias[i] = bias_table[rel_idx[n * NTOK + m] * HEADS + h];
    }
}

/* ================= mma fp16 / cp.async ================= */
__device__ __forceinline__ void mma16816(float* c, const uint32_t* a, const uint32_t* b) {
    asm volatile(
        "mma.sync.aligned.m16n8k16.row.col.f32.f16.f16.f32 "
        "{%0,%1,%2,%3}, {%4,%5,%6,%7}, {%8,%9}, {%0,%1,%2,%3};"
        : "+f"(c[0]), "+f"(c[1]), "+f"(c[2]), "+f"(c[3])
        : "r"(a[0]), "r"(a[1]), "r"(a[2]), "r"(a[3]), "r"(b[0]), "r"(b[1]));
}
__device__ __forceinline__ void cp16(uint32_t dst, const void* src) {
    asm volatile("cp.async.cg.shared.global [%0], [%1], 16;" :: "r"(dst), "l"(src));
}

/* ================ GEMM (exact R12 — best measured) ================ */
#define APAD   200
#define A_H    0
#define A_L    (128 * APAD * 2)                /* 51200  */
#define B_BASE (2 * 128 * APAD * 2)            /* 102400 */
#define B_STEP 27648
#define GEMM_SMEM (B_BASE + 2 * B_STEP)        /* 157696 */

__global__ __launch_bounds__(256, 1)
void gemm_fp16x2(const float* __restrict__ A,
                 const __half* __restrict__ B,
                 const float* __restrict__ bias,
                 float* __restrict__ C, int ldc, int NT)
{
    extern __shared__ char smc[];
    uint32_t sb;
    asm("{ .reg .u64 t; cvta.to.shared.u64 t, %1; cvt.u32.u64 %0, t; }" : "=r"(sb) : "l"(smc));

    const int tid = threadIdx.x, wid = tid >> 5, lane = tid & 31;
    const int mtile = blockIdx.x;
    const int wm = (wid & 3) * 32;
    const int wn = (wid >> 2) * 96;
    const int L  = 3 * NT;

    auto prefetch = [&](int idx) {
        int nt = idx / 3, kc = idx - nt * 3;
        const __half* bp = B + (size_t)nt * 192 * 192 + kc * 64;
        uint32_t dst = sb + B_BASE + (idx & 1) * B_STEP;
        #pragma unroll
        for (int it = 0; it < 6; it++) {
            int g = tid + it * 256;
            int row = g >> 3, c8 = g & 7;
            cp16(dst + row * 144 + c8 * 16, bp + row * 192 + c8 * 8);
        }
        asm volatile("cp.async.commit_group;" ::: "memory");
    };

    prefetch(0);
    if (L > 1) prefetch(1);

    /* ---- A: load 128x192 fp32, split hi/lo fp16 into smem (once) ---- */
    {
        const float* Abase = A + (size_t)mtile * 128 * 192;
        #pragma unroll
        for (int it = 0; it < 24; it++) {
            int g = tid + it * 256;
            int row = g / 48, c4 = (g % 48) * 4;
            float4 f = *(const float4*)(Abase + row * 192 + c4);
            __half hx = __float2half_rn(f.x), hy = __float2half_rn(f.y);
            __half hz = __float2half_rn(f.z), hw = __float2half_rn(f.w);
            float rx = f.x - __half2float(hx);
            float ry = f.y - __half2float(hy);
            float rz = f.z - __half2float(hz);
            float rw = f.w - __half2float(hw);
            *(uint2*)(smc + A_H + row * 400 + c4 * 2) =
                make_uint2(hpack(hx, hy), hpack(hz, hw));
            *(uint2*)(smc + A_L + row * 400 + c4 * 2) =
                make_uint2(hpack(__float2half_rn(rx), __float2half_rn(ry)),
                           hpack(__float2half_rn(rz), __float2half_rn(rw)));
        }
    }
    __syncthreads();

    float acc[2][12][4];

    for (int nt = 0; nt < NT; nt++) {
        #pragma unroll
        for (int mf = 0; mf < 2; mf++)
            #pragma unroll
            for (int nf = 0; nf < 12; nf++)
                #pragma unroll
                for (int j = 0; j < 4; j++) acc[mf][nf][j] = 0.f;

        for (int kc = 0; kc < 3; kc++) {
            const int idx = nt * 3 + kc;
            if (idx < L - 1) asm volatile("cp.async.wait_group 1;" ::: "memory");
            else             asm volatile("cp.async.wait_group 0;" ::: "memory");
            __syncthreads();

            const char* bb = smc + B_BASE + (idx & 1) * B_STEP;

            #pragma unroll
            for (int ks = 0; ks < 4; ks++) {
                const int kk  = ks * 16 + (lane & 3) * 2;
                const int kxg = kc * 64 + kk;

                uint32_t ah[2][4], al[2][4];
                #pragma unroll
                for (int mf = 0; mf < 2; mf++)
                    #pragma unroll
                    for (int j = 0; j < 4; j++) {
                        int rr = wm + mf * 16 + (lane >> 2) + (j & 1) * 8;
                        int kx = kxg + (j >> 1) * 8;
                        ah[mf][j] = *(const uint32_t*)(smc + A_H + rr * 400 + kx * 2);
                        al[mf][j] = *(const uint32_t*)(smc + A_L + rr * 400 + kx * 2);
                    }

                uint32_t bh[12][2];
                #pragma unroll
                for (int nf = 0; nf < 12; nf++) {
                    int n = wn + nf * 8 + (lane >> 2);
                    bh[nf][0] = *(const uint32_t*)(bb + n * 144 + kk * 2);
                    bh[nf][1] = *(const uint32_t*)(bb + n * 144 + (kk + 8) * 2);
                }

                #pragma unroll
                for (int mf = 0; mf < 2; mf++)
                    #pragma unroll
                    for (int nf = 0; nf < 12; nf++) {
                        mma16816(acc[mf][nf], ah[mf], bh[nf]);
                        mma16816(acc[mf][nf], al[mf], bh[nf]);
                    }
            }
            __syncthreads();
            if (idx + 2 < L) prefetch(idx + 2);
        }

        #pragma unroll
        for (int mf = 0; mf < 2; mf++) {
            size_t r0 = (size_t)mtile * 128 + wm + mf * 16 + (lane >> 2);
            #pragma unroll
            for (int nf = 0; nf < 12; nf++) {
                int c = nt * 192 + wn + nf * 8 + (lane & 3) * 2;
                float b0 = __ldg(bias + c), b1 = __ldg(bias + c + 1);
                *(float2*)(C + r0 * ldc + c) =
                    make_float2(acc[mf][nf][0] + b0, acc[mf][nf][1] + b1);
                *(float2*)(C + (r0 + 8) * ldc + c) =
                    make_float2(acc[mf][nf][2] + b0, acc[mf][nf][3] + b1);
            }
        }
    }
}

/* ================= K2: R12-shape attention, single-fp16 Q/K/P/V (fp32 accum) ===== */
__global__ __launch_bounds__(128, 3)
void attn_win()
{
    __shared__ __half sQh[64 * 36];
    __shared__ __half sKh[56 * 36];
    __shared__ __half sVh[32 * 66];

    const int tid  = threadIdx.x;
    const int wid  = tid >> 5, lane = tid & 31;
    const int b    = blockIdx.x;
    const int l4   = lane >> 2, lm = lane & 3;

    for (int i = tid; i < 64 * 36; i += 128) sQh[i] = __ushort_as_half(0);
    for (int i = tid; i < 56 * 36; i += 128) sKh[i] = __ushort_as_half(0);
    for (int i = tid; i < 32 * 66; i += 128) sVh[i] = __ushort_as_half(0);

    const float* qkvw = g_qkv + (size_t)b * (NTOK * 576);
    const int r0 = wid * 16 + l4;

    for (int h = 0; h < HEADS; h++) {
        __syncthreads();
        /* ---- convert: 49x32 q (scaled), k, v -> single fp16 ---- */
        for (int idx = tid; idx < NTOK * 32; idx += 128) {
            int r = idx >> 5, c = idx & 31;
            const float* rowp = qkvw + r * 576 + h * 32 + c;
            sQh[r * 36 + c] = __float2half_rn(rowp[0] * QSCALE);
            sKh[r * 36 + c] = __float2half_rn(rowp[192]);
            sVh[c * 66 + r] = __float2half_rn(rowp[384]);
        }
        __syncthreads();

        /* ---- Q a-frags ---- */
        uint32_t qh[2][4];
        #pragma unroll
        for (int kf = 0; kf < 2; kf++)
            #pragma unroll
            for (int j = 0; j < 4; j++) {
                int rr = r0 + (j & 1) * 8;
                int kx = kf * 16 + lm * 2 + (j >> 1) * 8;
                qh[kf][j] = *(const uint32_t*)&sQh[rr * 36 + kx];
            }

        /* ---- S = Q K^T (single-term) ---- */
        float acc[7][4];
        #pragma unroll
        for (int nf = 0; nf < 7; nf++)
            #pragma unroll
            for (int j = 0; j < 4; j++) acc[nf][j] = 0.f;

        #pragma unroll
        for (int nf = 0; nf < 7; nf++) {
            int n = nf * 8 + l4;
            #pragma unroll
            for (int kf = 0; kf < 2; kf++) {
                uint32_t bh[2];
                bh[0] = *(const uint32_t*)&sKh[n * 36 + kf * 16 + lm * 2];
                bh[1] = *(const uint32_t*)&sKh[n * 36 + kf * 16 + lm * 2 + 8];
                mma16816(acc[nf], qh[kf], bh);
            }
        }

        /* ---- softmax ---- */
        const int ra = r0, rb = r0 + 8;
        const float* biasA = g_bias + (h * NTOK + ra) * NTOK;
        const float* biasB = g_bias + (h * NTOK + rb) * NTOK;
        float ma = -1e30f, mb = -1e30f;
        #pragma unroll
        for (int nf = 0; nf < 7; nf++) {
            int c0 = nf * 8 + lm * 2, c1 = c0 + 1;
            float ba0 = (ra < NTOK && c0 < NTOK) ? __ldg(biasA + c0) : 0.f;
            float ba1 = (ra < NTOK && c1 < NTOK) ? __ldg(biasA + c1) : 0.f;
            float bb0 = (rb < NTOK && c0 < NTOK) ? __ldg(biasB + c0) : 0.f;
            float bb1 = (rb < NTOK && c1 < NTOK) ? __ldg(biasB + c1) : 0.f;
            acc[nf][0] = (c0 < NTOK) ? acc[nf][0] + ba0 : -1e30f;
            acc[nf][1] = (c1 < NTOK) ? acc[nf][1] + ba1 : -1e30f;
            acc[nf][2] = (c0 < NTOK) ? acc[nf][2] + bb0 : -1e30f;
            acc[nf][3] = (c1 < NTOK) ? acc[nf][3] + bb1 : -1e30f;
            ma = fmaxf(ma, fmaxf(acc[nf][0], acc[nf][1]));
            mb = fmaxf(mb, fmaxf(acc[nf][2], acc[nf][3]));
        }
        ma = fmaxf(ma, __shfl_xor_sync(0xffffffffu, ma, 1));
        ma = fmaxf(ma, __shfl_xor_sync(0xffffffffu, ma, 2));
        mb = fmaxf(mb, __shfl_xor_sync(0xffffffffu, mb, 1));
        mb = fmaxf(mb, __shfl_xor_sync(0xffffffffu, mb, 2));

        float sa = 0.f, sb2 = 0.f;
        #pragma unroll
        for (int nf = 0; nf < 7; nf++) {
            acc[nf][0] = __expf(acc[nf][0] - ma);
            acc[nf][1] = __expf(acc[nf][1] - ma);
            acc[nf][2] = __expf(acc[nf][2] - mb);
            acc[nf][3] = __expf(acc[nf][3] - mb);
            sa  += acc[nf][0] + acc[nf][1];
            sb2 += acc[nf][2] + acc[nf][3];
        }
        sa  += __shfl_xor_sync(0xffffffffu, sa, 1);
        sa  += __shfl_xor_sync(0xffffffffu, sa, 2);
        sb2 += __shfl_xor_sync(0xffffffffu, sb2, 1);
        sb2 += __shfl_xor_sync(0xffffffffu, sb2, 2);
        float inva = 1.f / sa, invb = 1.f / sb2;
        #pragma unroll
        for (int nf = 0; nf < 7; nf++) {
            acc[nf][0] *= inva; acc[nf][1] *= inva;
            acc[nf][2] *= invb; acc[nf][3] *= invb;
        }

        /* ---- P a-frags (single fp16) ---- */
        uint32_t pah[4][4];
        #pragma unroll
        for (int kf = 0; kf < 4; kf++) {
            #pragma unroll
            for (int half = 0; half < 2; half++) {
                int nf = 2 * kf + half;
                if (nf < 7) {
                    pah[kf][half * 2]     = hpack(__float2half_rn(acc[nf][0]),
                                                  __float2half_rn(acc[nf][1]));
                    pah[kf][half * 2 + 1] = hpack(__float2half_rn(acc[nf][2]),
                                                  __float2half_rn(acc[nf][3]));
                } else {
                    pah[kf][half * 2] = 0u; pah[kf][half * 2 + 1] = 0u;
                }
            }
        }

        /* ---- O = P V (single-term) ---- */
        float oacc[4][4];
        #pragma unroll
        for (int nf = 0; nf < 4; nf++)
            #pragma unroll
            for (int j = 0; j < 4; j++) oacc[nf][j] = 0.f;

        #pragma unroll
        for (int nf = 0; nf < 4; nf++) {
            int dh = nf * 8 + l4;
            #pragma unroll
            for (int kf = 0; kf < 4; kf++) {
                uint32_t bh[2];
                bh[0] = *(const uint32_t*)&sVh[dh * 66 + kf * 16 + lm * 2];
                bh[1] = *(const uint32_t*)&sVh[dh * 66 + kf * 16 + lm * 2 + 8];
                mma16816(oacc[nf], pah[kf], bh);
            }
        }

        if (ra < NTOK) {
            float* orow = g_attn + ((size_t)b * NTOK + ra) * DIM + h * DH;
            #pragma unroll
            for (int nf = 0; nf < 4; nf++)
                *(float2*)(orow + nf * 8 + lm * 2) = make_float2(oacc[nf][0], oacc[nf][1]);
        }
        if (rb < NTOK) {
            float* orow = g_attn + ((size_t)b * NTOK + rb) * DIM + h * DH;
            #pragma unroll
            for (int nf = 0; nf < 4; nf++)
                *(float2*)(orow + nf * 8 + lm * 2) = make_float2(oacc[nf][2], oacc[nf][3]);
        }
    }
}

/* ================= host ================= */
extern "C" void kernel_launch(void* const* d_in, const int* in_sizes, int n_in,
                              void* d_out, int out_size)
{
    const float* x          = (const float*)d_in[0];
    const float* qkv_w      = (const float*)d_in[1];
    const float* qkv_b      = (const float*)d_in[2];
    const float* proj_w     = (const float*)d_in[3];
    const float* proj_b     = (const float*)d_in[4];
    const float* bias_table = (const float*)d_in[5];
    const int*   rel_idx    = (const int*)d_in[6];
    float*       out        = (float*)d_out;

    const int nB = in_sizes[0] / (NTOK * DIM);       /* 4096 */
    const int mt = (nB * NTOK) / 128;                /* 1568 */

    void *p_qkv, *p_attn, *p_wq, *p_wp;
    cudaGetSymbolAddress(&p_qkv,  g_qkv);
    cudaGetSymbolAddress(&p_attn, g_attn);
    cudaGetSymbolAddress(&p_wq,   g_wq);
    cudaGetSymbolAddress(&p_wp,   g_wp);

    cudaFuncSetAttribute(gemm_fp16x2, cudaFuncAttributeMaxDynamicSharedMemorySize, GEMM_SMEM);

    prep_kernel<<<432, 256>>>(qkv_w, proj_w, bias_table, rel_idx);

    gemm_fp16x2<<<mt, 256, GEMM_SMEM>>>(
        x, (const __half*)p_wq, qkv_b, (float*)p_qkv, 576, 3);

    attn_win<<<nB, 128>>>();

    gemm_fp16x2<<<mt, 256, GEMM_SMEM>>>(
        (const float*)p_attn, (const __half*)p_wp, proj_b, out, 192, 1);
}

// round 16
// speedup vs baseline: 1.3847x; 1.2732x over previous
#include <cuda_runtime.h>
#include <cuda_fp16.h>
#include <cstdint>
#include <math.h>

#define NTOK   49
#define HEADS  6
#define DIM    192
#define DH     32
#define QSCALE 0.1767766952966369f

/* ================= device scratch (static: allocation-free) ================= */
__device__ __half  g_q16[200704u * 576u];   /* qkv out fp16 (q pre-scaled) 231 MB */
__device__ __half  g_a16[200704u * 192u];   /* attention out fp16          77 MB  */
__device__ __half  g_wq[576 * 192];
__device__ __half  g_wp[192 * 192];
__device__ float   g_bias[HEADS * NTOK * NTOK];

__device__ __forceinline__ uint32_t hpack(__half a, __half b) {
    return (uint32_t)__half_as_ushort(a) | ((uint32_t)__half_as_ushort(b) << 16);
}

/* ================= prep: weights -> fp16 (RN), materialize bias ================= */
__global__ void prep_kernel(const float* __restrict__ qkv_w, const float* __restrict__ proj_w,
                            const float* __restrict__ bias_table, const int* __restrict__ rel_idx)
{
    int i = blockIdx.x * 256 + threadIdx.x;
    if (i < 576 * 192) g_wq[i] = __float2half_rn(qkv_w[i]);
    if (i < 192 * 192) g_wp[i] = __float2half_rn(proj_w[i]);
    if (i < HEADS * NTOK * NTOK) {
        int m = i % NTOK, t = i / NTOK;
        int n = t % NTOK, h = t / NTOK;
        g_bias[i] = bias_table[rel_idx[n * NTOK + m] * HEADS + h];
    }
}

/* ================= mma fp16 / cp.async ================= */
__device__ __forceinline__ void mma16816(float* c, const uint32_t* a, const uint32_t* b) {
    asm volatile(
        "mma.sync.aligned.m16n8k16.row.col.f32.f16.f16.f32 "
        "{%0,%1,%2,%3}, {%4,%5,%6,%7}, {%8,%9}, {%0,%1,%2,%3};"
        : "+f"(c[0]), "+f"(c[1]), "+f"(c[2]), "+f"(c[3])
        : "r"(a[0]), "r"(a[1]), "r"(a[2]), "r"(a[3]), "r"(b[0]), "r"(b[1]));
}
__device__ __forceinline__ void cp16(uint32_t dst, const void* src) {
    asm volatile("cp.async.cg.shared.global [%0], [%1], 16;" :: "r"(dst), "l"(src));
}

/* ================ shared GEMM constants (A single fp16 now) ================ */
#define APAD_B 400                              /* A row stride in bytes (192*2 pad 400) */
#define A_H    0
#define B_BASE (128 * APAD_B)                   /* 51200 */
#define B_STEP 27648
#define GEMM_SMEM (B_BASE + 2 * B_STEP)         /* 106496 */

/* shared mainloop: A (single) resident, B double-buffered */
#define GEMM_MAINLOOP(L_)                                                          \
    for (int kc = 0; kc < 3; kc++) {                                               \
        const int idx = nt * 3 + kc;                                               \
        if (idx < (L_) - 1) asm volatile("cp.async.wait_group 1;" ::: "memory");   \
        else                asm volatile("cp.async.wait_group 0;" ::: "memory");   \
        __syncthreads();                                                           \
        const char* bb = smc + B_BASE + (idx & 1) * B_STEP;                        \
        _Pragma("unroll")                                                          \
        for (int ks = 0; ks < 4; ks++) {                                           \
            const int kk  = ks * 16 + (lane & 3) * 2;                              \
            const int kxg = kc * 64 + kk;                                          \
            uint32_t ah[2][4];                                                     \
            _Pragma("unroll")                                                      \
            for (int mf = 0; mf < 2; mf++)                                         \
                _Pragma("unroll")                                                  \
                for (int j = 0; j < 4; j++) {                                      \
                    int rr = wm + mf * 16 + (lane >> 2) + (j & 1) * 8;             \
                    int kx = kxg + (j >> 1) * 8;                                   \
                    ah[mf][j] = *(const uint32_t*)(smc + A_H + rr * APAD_B + kx * 2); \
                }                                                                  \
            uint32_t bh[12][2];                                                    \
            _Pragma("unroll")                                                      \
            for (int nf = 0; nf < 12; nf++) {                                      \
                int n = wn + nf * 8 + (lane >> 2);                                 \
                bh[nf][0] = *(const uint32_t*)(bb + n * 144 + kk * 2);             \
                bh[nf][1] = *(const uint32_t*)(bb + n * 144 + (kk + 8) * 2);       \
            }                                                                      \
            _Pragma("unroll")                                                      \
            for (int mf = 0; mf < 2; mf++)                                         \
                _Pragma("unroll")                                                  \
                for (int nf = 0; nf < 12; nf++)                                    \
                    mma16816(acc[mf][nf], ah[mf], bh[nf]);                         \
        }                                                                          \
        __syncthreads();                                                           \
        if (idx + 2 < (L_)) prefetch(idx + 2);                                     \
    }

/* ================ K1: qkv GEMM (fp32 A in, single fp16 out, q pre-scaled) ======== */
__global__ __launch_bounds__(256, 1)
void gemm_qkv(const float* __restrict__ A,
              const __half* __restrict__ B,
              const float* __restrict__ bias)
{
    extern __shared__ char smc[];
    uint32_t sb;
    asm("{ .reg .u64 t; cvta.to.shared.u64 t, %1; cvt.u32.u64 %0, t; }" : "=r"(sb) : "l"(smc));

    const int tid = threadIdx.x, wid = tid >> 5, lane = tid & 31;
    const int mtile = blockIdx.x;
    const int wm = (wid & 3) * 32;
    const int wn = (wid >> 2) * 96;

    auto prefetch = [&](int idx) {
        int nt2 = idx / 3, kc = idx - nt2 * 3;
        const __half* bp = B + (size_t)nt2 * 192 * 192 + kc * 64;
        uint32_t dst = sb + B_BASE + (idx & 1) * B_STEP;
        #pragma unroll
        for (int it = 0; it < 6; it++) {
            int g = tid + it * 256;
            int row = g >> 3, c8 = g & 7;
            cp16(dst + row * 144 + c8 * 16, bp + row * 192 + c8 * 8);
        }
        asm volatile("cp.async.commit_group;" ::: "memory");
    };

    prefetch(0);
    prefetch(1);

    /* A fp32 -> single fp16 smem, once */
    {
        const float* Abase = A + (size_t)mtile * 128 * 192;
        #pragma unroll
        for (int it = 0; it < 24; it++) {
            int g = tid + it * 256;
            int row = g / 48, c4 = (g % 48) * 4;
            float4 f = *(const float4*)(Abase + row * 192 + c4);
            *(uint2*)(smc + A_H + row * APAD_B + c4 * 2) =
                make_uint2(hpack(__float2half_rn(f.x), __float2half_rn(f.y)),
                           hpack(__float2half_rn(f.z), __float2half_rn(f.w)));
        }
    }
    __syncthreads();

    float acc[2][12][4];

    for (int nt = 0; nt < 3; nt++) {
        #pragma unroll
        for (int mf = 0; mf < 2; mf++)
            #pragma unroll
            for (int nf = 0; nf < 12; nf++)
                #pragma unroll
                for (int j = 0; j < 4; j++) acc[mf][nf][j] = 0.f;

        GEMM_MAINLOOP(9)

        /* epilogue: bias, q-scale, single fp16 stores */
        const int qcol = (nt == 0);
        #pragma unroll
        for (int mf = 0; mf < 2; mf++) {
            size_t r = (size_t)mtile * 128 + wm + mf * 16 + (lane >> 2);
            #pragma unroll
            for (int nf = 0; nf < 12; nf++) {
                int c = nt * 192 + wn + nf * 8 + (lane & 3) * 2;
                float b0 = __ldg(bias + c), b1 = __ldg(bias + c + 1);
                float v0 = acc[mf][nf][0] + b0, v1 = acc[mf][nf][1] + b1;
                float w0 = acc[mf][nf][2] + b0, w1 = acc[mf][nf][3] + b1;
                if (qcol) { v0 *= QSCALE; v1 *= QSCALE; w0 *= QSCALE; w1 *= QSCALE; }
                *(uint32_t*)&g_q16[r * 576 + c] =
                    hpack(__float2half_rn(v0), __float2half_rn(v1));
                *(uint32_t*)&g_q16[(r + 8) * 576 + c] =
                    hpack(__float2half_rn(w0), __float2half_rn(w1));
            }
        }
    }
}

/* ================ K3: proj GEMM (fp16 A via cp.async, fp32 out) ================ */
__global__ __launch_bounds__(256, 1)
void gemm_proj(const __half* __restrict__ Ain,
               const __half* __restrict__ B,
               const float* __restrict__ bias,
               float* __restrict__ C)
{
    extern __shared__ char smc[];
    uint32_t sb;
    asm("{ .reg .u64 t; cvta.to.shared.u64 t, %1; cvt.u32.u64 %0, t; }" : "=r"(sb) : "l"(smc));

    const int tid = threadIdx.x, wid = tid >> 5, lane = tid & 31;
    const int mtile = blockIdx.x;
    const int wm = (wid & 3) * 32;
    const int wn = (wid >> 2) * 96;

    auto prefetch = [&](int idx) {
        const __half* bp = B + idx * 64;        /* NT=1: idx == kc */
        uint32_t dst = sb + B_BASE + (idx & 1) * B_STEP;
        #pragma unroll
        for (int it = 0; it < 6; it++) {
            int g = tid + it * 256;
            int row = g >> 3, c8 = g & 7;
            cp16(dst + row * 144 + c8 * 16, bp + row * 192 + c8 * 8);
        }
        asm volatile("cp.async.commit_group;" ::: "memory");
    };

    /* A fp16: async copy (group 0) */
    {
        const __half* Ah = Ain + (size_t)mtile * 128 * 192;
        #pragma unroll
        for (int it = 0; it < 12; it++) {
            int g = tid + it * 256;             /* 3072 chunks of 16 B */
            int row = g / 24, c = g % 24;
            cp16(sb + A_H + row * APAD_B + c * 16, Ah + row * 192 + c * 8);
        }
        asm volatile("cp.async.commit_group;" ::: "memory");
    }
    prefetch(0);
    prefetch(1);

    float acc[2][12][4];
    {
        const int nt = 0;
        #pragma unroll
        for (int mf = 0; mf < 2; mf++)
            #pragma unroll
            for (int nf = 0; nf < 12; nf++)
                #pragma unroll
                for (int j = 0; j < 4; j++) acc[mf][nf][j] = 0.f;

        GEMM_MAINLOOP(3)

        #pragma unroll
        for (int mf = 0; mf < 2; mf++) {
            size_t r0 = (size_t)mtile * 128 + wm + mf * 16 + (lane >> 2);
            #pragma unroll
            for (int nf = 0; nf < 12; nf++) {
                int c = wn + nf * 8 + (lane & 3) * 2;
                float b0 = __ldg(bias + c), b1 = __ldg(bias + c + 1);
                *(float2*)(C + r0 * 192 + c) =
                    make_float2(acc[mf][nf][0] + b0, acc[mf][nf][1] + b1);
                *(float2*)(C + (r0 + 8) * 192 + c) =
                    make_float2(acc[mf][nf][2] + b0, acc[mf][nf][3] + b1);
            }
        }
    }
}

/* ================= K2: attention, fp16 in (pure copies) / fp16 out ================ */
__global__ __launch_bounds__(128, 3)
void attn_win()
{
    __shared__ __half sQh[64 * 36];
    __shared__ __half sKh[56 * 36];
    __shared__ __half sVh[32 * 66];

    const int tid  = threadIdx.x;
    const int wid  = tid >> 5, lane = tid & 31;
    const int b    = blockIdx.x;
    const int l4   = lane >> 2, lm = lane & 3;

    for (int i = tid; i < 64 * 36; i += 128) sQh[i] = __ushort_as_half(0);
    for (int i = tid; i < 56 * 36; i += 128) sKh[i] = __ushort_as_half(0);
    for (int i = tid; i < 32 * 66; i += 128) sVh[i] = __ushort_as_half(0);

    const __half* q16 = g_q16 + (size_t)b * (NTOK * 576);
    const int r0 = wid * 16 + l4;

    for (int h = 0; h < HEADS; h++) {
        __syncthreads();
        /* ---- load: pure fp16 copies ---- */
        for (int idx = tid; idx < NTOK * 16; idx += 128) {
            int r = idx >> 4, c2 = (idx & 15) << 1;
            uint32_t q2 = *(const uint32_t*)&q16[r * 576 + h * 32 + c2];
            uint32_t k2 = *(const uint32_t*)&q16[r * 576 + 192 + h * 32 + c2];
            uint32_t v2 = *(const uint32_t*)&q16[r * 576 + 384 + h * 32 + c2];
            *(uint32_t*)&sQh[r * 36 + c2] = q2;
            *(uint32_t*)&sKh[r * 36 + c2] = k2;
            sVh[c2 * 66 + r]       = __ushort_as_half((unsigned short)(v2 & 0xffffu));
            sVh[(c2 + 1) * 66 + r] = __ushort_as_half((unsigned short)(v2 >> 16));
        }
        __syncthreads();

        /* ---- Q a-frags ---- */
        uint32_t qh[2][4];
        #pragma unroll
        for (int kf = 0; kf < 2; kf++)
            #pragma unroll
            for (int j = 0; j < 4; j++) {
                int rr = r0 + (j & 1) * 8;
                int kx = kf * 16 + lm * 2 + (j >> 1) * 8;
                qh[kf][j] = *(const uint32_t*)&sQh[rr * 36 + kx];
            }

        /* ---- S = Q K^T ---- */
        float acc[7][4];
        #pragma unroll
        for (int nf = 0; nf < 7; nf++)
            #pragma unroll
            for (int j = 0; j < 4; j++) acc[nf][j] = 0.f;

        #pragma unroll
        for (int nf = 0; nf < 7; nf++) {
            int n = nf * 8 + l4;
            #pragma unroll
            for (int kf = 0; kf < 2; kf++) {
                uint32_t bh[2];
                bh[0] = *(const uint32_t*)&sKh[n * 36 + kf * 16 + lm * 2];
                bh[1] = *(const uint32_t*)&sKh[n * 36 + kf * 16 + lm * 2 + 8];
                mma16816(acc[nf], qh[kf], bh);
            }
        }

        /* ---- softmax ---- */
        const int ra = r0, rb = r0 + 8;
        const float* biasA = g_bias + (h * NTOK + ra) * NTOK;
        const float* biasB = g_bias + (h * NTOK + rb) * NTOK;
        float ma = -1e30f, mb = -1e30f;
        #pragma unroll
        for (int nf = 0; nf < 7; nf++) {
            int c0 = nf * 8 + lm * 2, c1 = c0 + 1;
            float ba0 = (ra < NTOK && c0 < NTOK) ? __ldg(biasA + c0) : 0.f;
            float ba1 = (ra < NTOK && c1 < NTOK) ? __ldg(biasA + c1) : 0.f;
            float bb0 = (rb < NTOK && c0 < NTOK) ? __ldg(biasB + c0) : 0.f;
            float bb1 = (rb < NTOK && c1 < NTOK) ? __ldg(biasB + c1) : 0.f;
            acc[nf][0] = (c0 < NTOK) ? acc[nf][0] + ba0 : -1e30f;
            acc[nf][1] = (c1 < NTOK) ? acc[nf][1] + ba1 : -1e30f;
            acc[nf][2] = (c0 < NTOK) ? acc[nf][2] + bb0 : -1e30f;
            acc[nf][3] = (c1 < NTOK) ? acc[nf][3] + bb1 : -1e30f;
            ma = fmaxf(ma, fmaxf(acc[nf][0], acc[nf][1]));
            mb = fmaxf(mb, fmaxf(acc[nf][2], acc[nf][3]));
        }
        ma = fmaxf(ma, __shfl_xor_sync(0xffffffffu, ma, 1));
        ma = fmaxf(ma, __shfl_xor_sync(0xffffffffu, ma, 2));
        mb = fmaxf(mb, __shfl_xor_sync(0xffffffffu, mb, 1));
        mb = fmaxf(mb, __shfl_xor_sync(0xffffffffu, mb, 2));

        float sa = 0.f, sb2 = 0.f;
        #pragma unroll
        for (int nf = 0; nf < 7; nf++) {
            acc[nf][0] = __expf(acc[nf][0] - ma);
            acc[nf][1] = __expf(acc[nf][1] - ma);
            acc[nf][2] = __expf(acc[nf][2] - mb);
            acc[nf][3] = __expf(acc[nf][3] - mb);
            sa  += acc[nf][0] + acc[nf][1];
            sb2 += acc[nf][2] + acc[nf][3];
        }
        sa  += __shfl_xor_sync(0xffffffffu, sa, 1);
        sa  += __shfl_xor_sync(0xffffffffu, sa, 2);
        sb2 += __shfl_xor_sync(0xffffffffu, sb2, 1);
        sb2 += __shfl_xor_sync(0xffffffffu, sb2, 2);
        float inva = 1.f / sa, invb = 1.f / sb2;
        #pragma unroll
        for (int nf = 0; nf < 7; nf++) {
            acc[nf][0] *= inva; acc[nf][1] *= inva;
            acc[nf][2] *= invb; acc[nf][3] *= invb;
        }

        /* ---- P a-frags (single fp16) ---- */
        uint32_t pah[4][4];
        #pragma unroll
        for (int kf = 0; kf < 4; kf++) {
            #pragma unroll
            for (int half = 0; half < 2; half++) {
                int nf = 2 * kf + half;
                if (nf < 7) {
                    pah[kf][half * 2]     = hpack(__float2half_rn(acc[nf][0]),
                                                  __float2half_rn(acc[nf][1]));
                    pah[kf][half * 2 + 1] = hpack(__float2half_rn(acc[nf][2]),
                                                  __float2half_rn(acc[nf][3]));
                } else {
                    pah[kf][half * 2] = 0u; pah[kf][half * 2 + 1] = 0u;
                }
            }
        }

        /* ---- O = P V ---- */
        float oacc[4][4];
        #pragma unroll
        for (int nf = 0; nf < 4; nf++)
            #pragma unroll
            for (int j = 0; j < 4; j++) oacc[nf][j] = 0.f;

        #pragma unroll
        for (int nf = 0; nf < 4; nf++) {
            int dh = nf * 8 + l4;
            #pragma unroll
            for (int kf = 0; kf < 4; kf++) {
                uint32_t bh[2];
                bh[0] = *(const uint32_t*)&sVh[dh * 66 + kf * 16 + lm * 2];
                bh[1] = *(const uint32_t*)&sVh[dh * 66 + kf * 16 + lm * 2 + 8];
                mma16816(oacc[nf], pah[kf], bh);
            }
        }

        /* ---- store O fp16 ---- */
        if (ra < NTOK) {
            size_t base = ((size_t)(b * NTOK + ra)) * DIM + h * DH;
            #pragma unroll
            for (int nf = 0; nf < 4; nf++)
                *(uint32_t*)&g_a16[base + nf * 8 + lm * 2] =
                    hpack(__float2half_rn(oacc[nf][0]), __float2half_rn(oacc[nf][1]));
        }
        if (rb < NTOK) {
            size_t base = ((size_t)(b * NTOK + rb)) * DIM + h * DH;
            #pragma unroll
            for (int nf = 0; nf < 4; nf++)
                *(uint32_t*)&g_a16[base + nf * 8 + lm * 2] =
                    hpack(__float2half_rn(oacc[nf][2]), __float2half_rn(oacc[nf][3]));
        }
    }
}

/* ================= host ================= */
extern "C" void kernel_launch(void* const* d_in, const int* in_sizes, int n_in,
                              void* d_out, int out_size)
{
    const float* x          = (const float*)d_in[0];
    const float* qkv_w      = (const float*)d_in[1];
    const float* qkv_b      = (const float*)d_in[2];
    const float* proj_w     = (const float*)d_in[3];
    const float* proj_b     = (const float*)d_in[4];
    const float* bias_table = (const float*)d_in[5];
    const int*   rel_idx    = (const int*)d_in[6];
    float*       out        = (float*)d_out;

    const int nB = in_sizes[0] / (NTOK * DIM);       /* 4096 */
    const int mt = (nB * NTOK) / 128;                /* 1568 */

    void *p_wq, *p_wp, *p_a16;
    cudaGetSymbolAddress(&p_wq,  g_wq);
    cudaGetSymbolAddress(&p_wp,  g_wp);
    cudaGetSymbolAddress(&p_a16, g_a16);

    cudaFuncSetAttribute(gemm_qkv,  cudaFuncAttributeMaxDynamicSharedMemorySize, GEMM_SMEM);
    cudaFuncSetAttribute(gemm_proj, cudaFuncAttributeMaxDynamicSharedMemorySize, GEMM_SMEM);

    prep_kernel<<<432, 256>>>(qkv_w, proj_w, bias_table, rel_idx);

    gemm_qkv<<<mt, 256, GEMM_SMEM>>>(x, (const __half*)p_wq, qkv_b);

    attn_win<<<nB, 128>>>();

    gemm_proj<<<mt, 256, GEMM_SMEM>>>((const __half*)p_a16, (const __half*)p_wp,
                                      proj_b, out);
}